// round 6
// baseline (speedup 1.0000x reference)
#include <cuda_runtime.h>
#include <cuda_bf16.h>
#include <math.h>
#include <stdint.h>

#define B_  2
#define S_  2048
#define D_  1024
#define H_  16
#define DK_ 64
#define SCALE_ 0.125f
#define LOG2E_ 1.44269504f
#define TNEG_ (-86562.0f)   // -60000 * log2(e)

// ---------------- scratch ----------------
__device__ __nv_bfloat16 g_xh[B_ * S_ * D_];
__device__ __nv_bfloat16 g_xl[B_ * S_ * D_];
__device__ __nv_bfloat16 g_wqkvh[3 * D_ * D_];
__device__ __nv_bfloat16 g_wqkvl[3 * D_ * D_];
__device__ __nv_bfloat16 g_wouth[D_ * D_];
__device__ __nv_bfloat16 g_woutl[D_ * D_];
__device__ __nv_bfloat16 g_qkvh[B_ * S_ * 3 * D_];
__device__ __nv_bfloat16 g_qkvl[B_ * S_ * 3 * D_];
__device__ __nv_bfloat16 g_ctxh[B_ * S_ * D_];
__device__ __nv_bfloat16 g_ctxl[B_ * S_ * D_];

// ================= helpers =================
__device__ __forceinline__ uint32_t smem_u32(const void* p) {
    uint32_t a;
    asm("{ .reg .u64 t; cvta.to.shared.u64 t, %1; cvt.u32.u64 %0, t; }" : "=r"(a) : "l"(p));
    return a;
}
#define CP16(dst, src) asm volatile("cp.async.cg.shared.global [%0], [%1], 16;" :: "r"(dst), "l"(src) : "memory")
#define CP_COMMIT()    asm volatile("cp.async.commit_group;" ::: "memory")
#define CP_WAIT0()     asm volatile("cp.async.wait_group 0;" ::: "memory")

__device__ __forceinline__ void ldsm4(uint32_t* r, uint32_t addr) {
    asm volatile("ldmatrix.sync.aligned.m8n8.x4.shared.b16 {%0,%1,%2,%3}, [%4];"
        : "=r"(r[0]), "=r"(r[1]), "=r"(r[2]), "=r"(r[3]) : "r"(addr));
}
__device__ __forceinline__ void ldsm4t(uint32_t* r, uint32_t addr) {
    asm volatile("ldmatrix.sync.aligned.m8n8.x4.trans.shared.b16 {%0,%1,%2,%3}, [%4];"
        : "=r"(r[0]), "=r"(r[1]), "=r"(r[2]), "=r"(r[3]) : "r"(addr));
}
__device__ __forceinline__ void mma16816(float* d, const uint32_t* a, const uint32_t* b) {
    asm volatile("mma.sync.aligned.m16n8k16.row.col.f32.bf16.bf16.f32 "
        "{%0,%1,%2,%3}, {%4,%5,%6,%7}, {%8,%9}, {%0,%1,%2,%3};"
        : "+f"(d[0]), "+f"(d[1]), "+f"(d[2]), "+f"(d[3])
        : "r"(a[0]), "r"(a[1]), "r"(a[2]), "r"(a[3]), "r"(b[0]), "r"(b[1]));
}
__device__ __forceinline__ float ex2(float x) {
    float y; asm("ex2.approx.ftz.f32 %0, %1;" : "=f"(y) : "f"(x)); return y;
}
__device__ __forceinline__ void split2(float a, float b, uint32_t& hi, uint32_t& lo) {
    __nv_bfloat16 ha = __float2bfloat16(a), hb = __float2bfloat16(b);
    hi = (uint32_t)__bfloat16_as_ushort(ha) | ((uint32_t)__bfloat16_as_ushort(hb) << 16);
    __nv_bfloat16 la = __float2bfloat16(a - __bfloat162float(ha));
    __nv_bfloat16 lb = __float2bfloat16(b - __bfloat162float(hb));
    lo = (uint32_t)__bfloat16_as_ushort(la) | ((uint32_t)__bfloat16_as_ushort(lb) << 16);
}

// ================= split fp32 -> bf16 hi/lo =================
__global__ void split_bf16(const float* __restrict__ in, __nv_bfloat16* __restrict__ hi,
                           __nv_bfloat16* __restrict__ lo, int n4) {
    int i = blockIdx.x * blockDim.x + threadIdx.x;
    if (i >= n4) return;
    float4 v = ((const float4*)in)[i];
    uint32_t h0, l0, h1, l1;
    split2(v.x, v.y, h0, l0);
    split2(v.z, v.w, h1, l1);
    ((uint2*)hi)[i] = make_uint2(h0, h1);
    ((uint2*)lo)[i] = make_uint2(l0, l1);
}

// ================= warp-MMA split-bf16 GEMM — flash-shaped =================
// CTA: 64(M) x 128(N), 128 threads (4 warps), warp = 16 rows x 128 cols.
// BK=64, 2-stage cp.async, padded 144B rows (conflict-free ldsm).
#define GSTRIDE_B 144
#define GA_TILE (64 * GSTRIDE_B)        // 9216
#define GB_TILE (128 * GSTRIDE_B)       // 18432
#define GAH_OFF 0
#define GAL_OFF GA_TILE
#define GBH_OFF (2 * GA_TILE)
#define GBL_OFF (2 * GA_TILE + GB_TILE)
#define GSTAGE_B (2 * GA_TILE + 2 * GB_TILE)   // 55296

__global__ __launch_bounds__(128, 2)
void gemm_mma(const __nv_bfloat16* __restrict__ Ah, const __nv_bfloat16* __restrict__ Al,
              const __nv_bfloat16* __restrict__ Bh, const __nv_bfloat16* __restrict__ Bl,
              float* __restrict__ Cf, __nv_bfloat16* __restrict__ Ch, __nv_bfloat16* __restrict__ Cl,
              int N, int K, int split_out)
{
    extern __shared__ char sm[];
    const int tid = threadIdx.x, wid = tid >> 5, lane = tid & 31;
    uint32_t sbase = smem_u32(sm);

    const char* gAh = (const char*)(Ah + (size_t)blockIdx.y * 64 * K);
    const char* gAl = (const char*)(Al + (size_t)blockIdx.y * 64 * K);
    const char* gBh = (const char*)(Bh + (size_t)blockIdx.x * 128 * K);
    const char* gBl = (const char*)(Bl + (size_t)blockIdx.x * 128 * K);

    float acc[16][4] = {};

    auto load_stage = [&](int j) {
        uint32_t sb = sbase + (j & 1) * GSTAGE_B;
        const size_t gc = (size_t)j * 128;   // byte offset into K (64 bf16)
        // A tiles: 64 rows x 8 chunks = 512 chunks each
        #pragma unroll
        for (int i = 0; i < 4; i++) {
            int c = tid + i * 128;
            int row = c >> 3, col = c & 7;
            uint32_t so = row * GSTRIDE_B + col * 16;
            size_t go = gc + (size_t)row * K * 2 + col * 16;
            CP16(sb + GAH_OFF + so, gAh + go);
            CP16(sb + GAL_OFF + so, gAl + go);
        }
        // B tiles: 128 rows x 8 chunks = 1024 chunks each
        #pragma unroll
        for (int i = 0; i < 8; i++) {
            int c = tid + i * 128;
            int row = c >> 3, col = c & 7;
            uint32_t so = row * GSTRIDE_B + col * 16;
            size_t go = gc + (size_t)row * K * 2 + col * 16;
            CP16(sb + GBH_OFF + so, gBh + go);
            CP16(sb + GBL_OFF + so, gBl + go);
        }
    };

    load_stage(0); CP_COMMIT();
    const int NK = K / 64;

    const uint32_t arow = (lane & 15), acs = (lane >> 4) * 16;
    const uint32_t brow = (lane & 7) + (lane >> 4) * 8, bcs = ((lane >> 3) & 1) * 16;

    for (int j = 0; j < NK; j++) {
        CP_WAIT0();
        __syncthreads();
        if (j + 1 < NK) { load_stage(j + 1); CP_COMMIT(); }

        uint32_t sb = sbase + (j & 1) * GSTAGE_B;
        uint32_t aH = sb + GAH_OFF + wid * 16 * GSTRIDE_B;
        uint32_t aL = sb + GAL_OFF + wid * 16 * GSTRIDE_B;
        uint32_t bH = sb + GBH_OFF;
        uint32_t bL = sb + GBL_OFF;

        #pragma unroll
        for (int ks = 0; ks < 4; ks++) {
            uint32_t ah[4], al[4];
            ldsm4(ah, aH + arow * GSTRIDE_B + ks * 32 + acs);
            ldsm4(al, aL + arow * GSTRIDE_B + ks * 32 + acs);
            #pragma unroll
            for (int half = 0; half < 2; half++) {
                uint32_t bh[4][4], bl[4][4];
                #pragma unroll
                for (int np = 0; np < 4; np++) {
                    uint32_t roff = (half * 64 + np * 16 + brow) * GSTRIDE_B + ks * 32 + bcs;
                    ldsm4(bh[np], bH + roff);
                    ldsm4(bl[np], bL + roff);
                }
                float* a8 = &acc[half * 8][0];
                #pragma unroll
                for (int np = 0; np < 4; np++) {
                    mma16816(a8 + (2 * np) * 4,     ah, &bh[np][0]);
                    mma16816(a8 + (2 * np + 1) * 4, ah, &bh[np][2]);
                }
                #pragma unroll
                for (int np = 0; np < 4; np++) {
                    mma16816(a8 + (2 * np) * 4,     ah, &bl[np][0]);
                    mma16816(a8 + (2 * np + 1) * 4, ah, &bl[np][2]);
                }
                #pragma unroll
                for (int np = 0; np < 4; np++) {
                    mma16816(a8 + (2 * np) * 4,     al, &bh[np][0]);
                    mma16816(a8 + (2 * np + 1) * 4, al, &bh[np][2]);
                }
            }
        }
    }

    // epilogue: warp w -> rows blockIdx.y*64 + w*16 + (lane>>2) (+8), cols nt*8 + (lane&3)*2
    const int rb = blockIdx.y * 64 + wid * 16 + (lane >> 2);
    const int cb = blockIdx.x * 128 + (lane & 3) * 2;
    #pragma unroll
    for (int half = 0; half < 2; half++) {
        int r = rb + half * 8;
        #pragma unroll
        for (int nt = 0; nt < 16; nt++) {
            int c = cb + nt * 8;
            float v0 = acc[nt][half * 2 + 0];
            float v1 = acc[nt][half * 2 + 1];
            if (split_out) {
                uint32_t hi, lo;
                split2(v0, v1, hi, lo);
                *(uint32_t*)(Ch + (size_t)r * N + c) = hi;
                *(uint32_t*)(Cl + (size_t)r * N + c) = lo;
            } else {
                *(float2*)(Cf + (size_t)r * N + c) = make_float2(v0, v1);
            }
        }
    }
}

// ================= flash attention, warp-MMA split-bf16 (unchanged) =================
#define FSTRIDE_B 144
#define FTILE_B (64 * FSTRIDE_B)        // 9216
#define FSTAGE_B (4 * FTILE_B)
#define FQ_OFF 0
#define FST_OFF (2 * FTILE_B)
#define FMS_OFF (FST_OFF + 2 * FSTAGE_B)
#define FSMEM_TOTAL (FMS_OFF + 128)

__global__ __launch_bounds__(128, 2)
void flash_mma(const __nv_bfloat16* __restrict__ qh, const __nv_bfloat16* __restrict__ ql,
               const unsigned char* __restrict__ mask,
               __nv_bfloat16* __restrict__ cth, __nv_bfloat16* __restrict__ ctl)
{
    extern __shared__ char sm[];
    const int tid = threadIdx.x, wid = tid >> 5, lane = tid & 31;
    const int bh = blockIdx.y, b = bh >> 4, h = bh & 15;
    const int q0 = blockIdx.x * 64;
    uint32_t sbase = smem_u32(sm);
    const uint32_t QH = sbase + FQ_OFF, QL = QH + FTILE_B;
    const uint32_t STG = sbase + FST_OFF;

    const size_t rs = 3 * D_;
    const char* qbh = (const char*)(qh + ((size_t)b * S_ + q0) * rs + h * 64);
    const char* qbl = (const char*)(ql + ((size_t)b * S_ + q0) * rs + h * 64);
    const char* kbh = (const char*)(qh + (size_t)b * S_ * rs + D_ + h * 64);
    const char* kbl = (const char*)(ql + (size_t)b * S_ * rs + D_ + h * 64);
    const char* vbh = (const char*)(qh + (size_t)b * S_ * rs + 2 * D_ + h * 64);
    const char* vbl = (const char*)(ql + (size_t)b * S_ * rs + 2 * D_ + h * 64);

    auto load_kv = [&](int j) {
        uint32_t sb = STG + (j & 1) * FSTAGE_B;
        size_t gk = (size_t)j * 64 * rs * 2;
        #pragma unroll
        for (int i = 0; i < 4; i++) {
            int c = tid + i * 128;
            int row = c >> 3, col = c & 7;
            size_t go = gk + (size_t)row * rs * 2 + col * 16;
            uint32_t so = row * FSTRIDE_B + col * 16;
            CP16(sb + 0 * FTILE_B + so, kbh + go);
            CP16(sb + 1 * FTILE_B + so, kbl + go);
            CP16(sb + 2 * FTILE_B + so, vbh + go);
            CP16(sb + 3 * FTILE_B + so, vbl + go);
        }
    };
    auto store_mask = [&](int j) {
        if (tid < 16) {
            uint32_t v = *(const uint32_t*)(mask + (size_t)b * S_ + j * 64 + tid * 4);
            *(uint32_t*)(sm + FMS_OFF + (j & 1) * 64 + tid * 4) = v;
        }
    };

    #pragma unroll
    for (int i = 0; i < 4; i++) {
        int c = tid + i * 128;
        int row = c >> 3, col = c & 7;
        uint32_t so = row * FSTRIDE_B + col * 16;
        CP16(QH + so, qbh + (size_t)row * rs * 2 + col * 16);
        CP16(QL + so, qbl + (size_t)row * rs * 2 + col * 16);
    }
    load_kv(0); CP_COMMIT();
    store_mask(0);

    uint32_t qfh[4][4], qfl[4][4];
    float o[8][4] = {};
    float m0 = -1e30f, m1 = -1e30f, l0 = 0.0f, l1 = 0.0f;

    const uint32_t arow = (lane & 15), acs = (lane >> 4) * 16;
    const uint32_t brow = (lane & 7) + (lane >> 4) * 8, bcs = ((lane >> 3) & 1) * 16;

    for (int kt = 0; kt < S_ / 64; kt++) {
        CP_WAIT0();
        __syncthreads();
        if (kt == 0) {
            #pragma unroll
            for (int ks = 0; ks < 4; ks++) {
                ldsm4(qfh[ks], QH + (wid * 16 + arow) * FSTRIDE_B + ks * 32 + acs);
                ldsm4(qfl[ks], QL + (wid * 16 + arow) * FSTRIDE_B + ks * 32 + acs);
            }
        }
        if (kt + 1 < S_ / 64) { load_kv(kt + 1); CP_COMMIT(); store_mask(kt + 1); }

        uint32_t sb = STG + (kt & 1) * FSTAGE_B;
        uint32_t KH = sb, KL = sb + FTILE_B, VH = sb + 2 * FTILE_B, VL = sb + 3 * FTILE_B;

        float s[8][4] = {};
        #pragma unroll
        for (int ks = 0; ks < 4; ks++) {
            uint32_t kh[4][4], kl[4][4];
            #pragma unroll
            for (int np = 0; np < 4; np++) {
                ldsm4(kh[np], KH + (np * 16 + brow) * FSTRIDE_B + ks * 32 + bcs);
                ldsm4(kl[np], KL + (np * 16 + brow) * FSTRIDE_B + ks * 32 + bcs);
            }
            #pragma unroll
            for (int np = 0; np < 4; np++) {
                mma16816(s[2 * np],     qfh[ks], &kh[np][0]);
                mma16816(s[2 * np + 1], qfh[ks], &kh[np][2]);
            }
            #pragma unroll
            for (int np = 0; np < 4; np++) {
                mma16816(s[2 * np],     qfh[ks], &kl[np][0]);
                mma16816(s[2 * np + 1], qfh[ks], &kl[np][2]);
            }
            #pragma unroll
            for (int np = 0; np < 4; np++) {
                mma16816(s[2 * np],     qfl[ks], &kh[np][0]);
                mma16816(s[2 * np + 1], qfl[ks], &kh[np][2]);
            }
        }

        const float CM = SCALE_ * LOG2E_;
        float rmax0 = -1e30f, rmax1 = -1e30f;
        #pragma unroll
        for (int nt = 0; nt < 8; nt++) {
            unsigned short mm = *(const unsigned short*)(sm + FMS_OFF + (kt & 1) * 64 + nt * 8 + (lane & 3) * 2);
            bool k0m = (mm & 0xFF) != 0, k1m = (mm >> 8) != 0;
            s[nt][0] = k0m ? TNEG_ : s[nt][0] * CM;
            s[nt][1] = k1m ? TNEG_ : s[nt][1] * CM;
            s[nt][2] = k0m ? TNEG_ : s[nt][2] * CM;
            s[nt][3] = k1m ? TNEG_ : s[nt][3] * CM;
            rmax0 = fmaxf(rmax0, fmaxf(s[nt][0], s[nt][1]));
            rmax1 = fmaxf(rmax1, fmaxf(s[nt][2], s[nt][3]));
        }
        rmax0 = fmaxf(rmax0, __shfl_xor_sync(0xffffffffu, rmax0, 1));
        rmax0 = fmaxf(rmax0, __shfl_xor_sync(0xffffffffu, rmax0, 2));
        rmax1 = fmaxf(rmax1, __shfl_xor_sync(0xffffffffu, rmax1, 1));
        rmax1 = fmaxf(rmax1, __shfl_xor_sync(0xffffffffu, rmax1, 2));
        float mn0 = fmaxf(m0, rmax0), mn1 = fmaxf(m1, rmax1);
        float cr0 = ex2(m0 - mn0), cr1 = ex2(m1 - mn1);
        m0 = mn0; m1 = mn1;
        float ps0 = 0.0f, ps1 = 0.0f;
        #pragma unroll
        for (int nt = 0; nt < 8; nt++) {
            s[nt][0] = ex2(s[nt][0] - mn0);
            s[nt][1] = ex2(s[nt][1] - mn0);
            s[nt][2] = ex2(s[nt][2] - mn1);
            s[nt][3] = ex2(s[nt][3] - mn1);
            ps0 += s[nt][0] + s[nt][1];
            ps1 += s[nt][2] + s[nt][3];
        }
        ps0 += __shfl_xor_sync(0xffffffffu, ps0, 1);
        ps0 += __shfl_xor_sync(0xffffffffu, ps0, 2);
        ps1 += __shfl_xor_sync(0xffffffffu, ps1, 1);
        ps1 += __shfl_xor_sync(0xffffffffu, ps1, 2);
        l0 = l0 * cr0 + ps0;
        l1 = l1 * cr1 + ps1;
        #pragma unroll
        for (int nt = 0; nt < 8; nt++) {
            o[nt][0] *= cr0; o[nt][1] *= cr0;
            o[nt][2] *= cr1; o[nt][3] *= cr1;
        }

        uint32_t ph[4][4], pl[4][4];
        #pragma unroll
        for (int kp = 0; kp < 4; kp++) {
            split2(s[2 * kp][0],     s[2 * kp][1],     ph[kp][0], pl[kp][0]);
            split2(s[2 * kp][2],     s[2 * kp][3],     ph[kp][1], pl[kp][1]);
            split2(s[2 * kp + 1][0], s[2 * kp + 1][1], ph[kp][2], pl[kp][2]);
            split2(s[2 * kp + 1][2], s[2 * kp + 1][3], ph[kp][3], pl[kp][3]);
        }

        #pragma unroll
        for (int kp = 0; kp < 4; kp++) {
            uint32_t vh[4][4], vl[4][4];
            uint32_t krow = kp * 16 + (lane & 15);
            uint32_t dbyte = (lane >> 4) * 16;
            #pragma unroll
            for (int dp = 0; dp < 4; dp++) {
                ldsm4t(vh[dp], VH + krow * FSTRIDE_B + dp * 32 + dbyte);
                ldsm4t(vl[dp], VL + krow * FSTRIDE_B + dp * 32 + dbyte);
            }
            #pragma unroll
            for (int dp = 0; dp < 4; dp++) {
                mma16816(o[2 * dp],     ph[kp], &vh[dp][0]);
                mma16816(o[2 * dp + 1], ph[kp], &vh[dp][2]);
            }
            #pragma unroll
            for (int dp = 0; dp < 4; dp++) {
                mma16816(o[2 * dp],     ph[kp], &vl[dp][0]);
                mma16816(o[2 * dp + 1], ph[kp], &vl[dp][2]);
            }
            #pragma unroll
            for (int dp = 0; dp < 4; dp++) {
                mma16816(o[2 * dp],     pl[kp], &vh[dp][0]);
                mma16816(o[2 * dp + 1], pl[kp], &vh[dp][2]);
            }
        }
    }

    float il0 = 1.0f / l0, il1 = 1.0f / l1;
    int r0 = q0 + wid * 16 + (lane >> 2);
    int cbase = h * 64 + (lane & 3) * 2;
    #pragma unroll
    for (int nt = 0; nt < 8; nt++) {
        int c = cbase + nt * 8;
        uint32_t hi, lo;
        size_t i0 = ((size_t)b * S_ + r0) * D_ + c;
        split2(o[nt][0] * il0, o[nt][1] * il0, hi, lo);
        *(uint32_t*)(cth + i0) = hi;
        *(uint32_t*)(ctl + i0) = lo;
        size_t i1 = i0 + 8 * D_;
        split2(o[nt][2] * il1, o[nt][3] * il1, hi, lo);
        *(uint32_t*)(cth + i1) = hi;
        *(uint32_t*)(ctl + i1) = lo;
    }
}

// ---------------- launch ----------------
extern "C" void kernel_launch(void* const* d_in, const int* in_sizes, int n_in,
                              void* d_out, int out_size)
{
    const float* x    = (const float*)d_in[0];
    const float* Wqkv = (const float*)d_in[1];
    const float* Wout = (const float*)d_in[2];
    const unsigned char* mask = (const unsigned char*)d_in[3];
    float* out = (float*)d_out;

    __nv_bfloat16 *xh, *xl, *wqh, *wql, *woh, *wol, *qvh, *qvl, *cth, *ctl;
    cudaGetSymbolAddress((void**)&xh,  g_xh);
    cudaGetSymbolAddress((void**)&xl,  g_xl);
    cudaGetSymbolAddress((void**)&wqh, g_wqkvh);
    cudaGetSymbolAddress((void**)&wql, g_wqkvl);
    cudaGetSymbolAddress((void**)&woh, g_wouth);
    cudaGetSymbolAddress((void**)&wol, g_woutl);
    cudaGetSymbolAddress((void**)&qvh, g_qkvh);
    cudaGetSymbolAddress((void**)&qvl, g_qkvl);
    cudaGetSymbolAddress((void**)&cth, g_ctxh);
    cudaGetSymbolAddress((void**)&ctl, g_ctxl);

    const int gemm_smem = 2 * GSTAGE_B;     // 110592 -> 2 CTAs/SM
    const int flash_smem = FSMEM_TOTAL;
    static int attrs_set = 0;
    if (!attrs_set) {
        cudaFuncSetAttribute(gemm_mma, cudaFuncAttributeMaxDynamicSharedMemorySize, gemm_smem);
        cudaFuncSetAttribute(flash_mma, cudaFuncAttributeMaxDynamicSharedMemorySize, flash_smem);
        attrs_set = 1;
    }

    {
        int n4x = (B_ * S_ * D_) / 4;
        split_bf16<<<(n4x + 255) / 256, 256>>>(x, xh, xl, n4x);
        int n4w = (3 * D_ * D_) / 4;
        split_bf16<<<(n4w + 255) / 256, 256>>>(Wqkv, wqh, wql, n4w);
        int n4o = (D_ * D_) / 4;
        split_bf16<<<(n4o + 255) / 256, 256>>>(Wout, woh, wol, n4o);
    }

    {
        dim3 grid((3 * D_) / 128, (B_ * S_) / 64);
        gemm_mma<<<grid, 128, gemm_smem>>>(xh, xl, wqh, wql, nullptr, qvh, qvl, 3 * D_, D_, 1);
    }
    {
        dim3 grid(S_ / 64, B_ * H_);
        flash_mma<<<grid, 128, flash_smem>>>(qvh, qvl, mask, cth, ctl);
    }
    {
        dim3 grid(D_ / 128, (B_ * S_) / 64);
        gemm_mma<<<grid, 128, gemm_smem>>>(cth, ctl, woh, wol, out, nullptr, nullptr, D_, D_, 0);
    }
}